// round 13
// baseline (speedup 1.0000x reference)
#include <cuda_runtime.h>

#define SCOARSE 256
#define SFINE   128
#define WPB     8
#define ZSTEP   0.0078125f          // exact log10 step of coarse grid
#define HZSTEP  0.00390625f         // ZSTEP/2
#define FLOORW  3.90625e-7f         // 1e-4 / 256
#define CSTEP   0.025952563f        // ZSTEP * log2(10)
#define ZMUL    1.0181517217f       // 10^ZSTEP
#define SSC     (-5.7707801636f)    // -4 * log2(e)
#define EC      (-0.2817763752f)    // -25 * ZSTEP * log2(e): om-arg scale per q-unit

__device__ __forceinline__ float ex2(float x)   { float r; asm("ex2.approx.f32 %0, %1;"   : "=f"(r) : "f"(x)); return r; }
__device__ __forceinline__ float rcpa(float x)  { float r; asm("rcp.approx.f32 %0, %1;"   : "=f"(r) : "f"(x)); return r; }
__device__ __forceinline__ float rsqa(float x)  { float r; asm("rsqrt.approx.f32 %0, %1;" : "=f"(r) : "f"(x)); return r; }
__device__ __forceinline__ float tanha(float x) { float r; asm("tanh.approx.f32 %0, %1;"  : "=f"(r) : "f"(x)); return r; }

__global__ __launch_bounds__(WPB * 32)
void nerf_kernel(const float* __restrict__ rays_o,
                 const float* __restrict__ rays_d,
                 const float* __restrict__ bg_color,
                 float* __restrict__ out, int N)
{
    const unsigned FULL = 0xffffffffu;
    const int lane = threadIdx.x & 31;
    const int w    = threadIdx.x >> 5;
    const int ray  = blockIdx.x * WPB + w;
    if (ray >= N) return;

    __shared__ float sCD[WPB][SCOARSE];   // INCLUSIVE raw cumsum (16B-aligned rows)

    // ---- ray setup ----
    float ox = rays_o[ray*3+0], oy = rays_o[ray*3+1], oz = rays_o[ray*3+2];
    float dx = rays_d[ray*3+0], dy = rays_d[ray*3+1], dz = rays_d[ray*3+2];
    float bgx = bg_color[0], bgy = bg_color[1], bgz = bg_color[2];
    {
        float inv = rsqa(dx*dx + dy*dy + dz*dz);
        dx *= inv; dy *= inv; dz *= inv;
    }
    // |o + d z|^2 = a + b z + z^2  (d normalized)
    float a  = fmaf(ox, ox, fmaf(oy, oy, oz * oz));
    float od = fmaf(ox, dx, fmaf(oy, dy, oz * dz));
    float b  = od + od;

    // =================================================================
    // COARSE: 256 samples, 8 per lane. n2 via the ray quadratic only.
    // om = 1-alpha = ex2( EC * ex2(SSC*ss) ). Product-scan transmittance.
    // =================================================================
    float om8[8];
    float z = ex2((float)(lane * 8 - 128) * CSTEP);
#pragma unroll
    for (int j = 0; j < 8; ++j) {
        if (j) z *= ZMUL;
        float n2 = fmaf(z, z + b, a);
        float g  = 2.0f - rsqa(n2);
        float ss = (n2 > 1.0f) ? g * g : n2;
        float e1 = ex2(ss * SSC);
        om8[j] = ex2(e1 * EC);
    }
    if (lane == 31) om8[7] = 1.0f;            // last delta = 0 -> alpha = 0
    float cp = ((om8[0]*om8[1])*(om8[2]*om8[3]))*((om8[4]*om8[5])*(om8[6]*om8[7]));

    // inclusive product scan of chunk products -> transmittance
    float incl = cp;
#pragma unroll
    for (int off = 1; off < 32; off <<= 1) {
        float v = __shfl_up_sync(FULL, incl, off);
        if (lane >= off) incl *= v;
    }
    float trans = __shfl_up_sync(FULL, incl, 1);
    if (lane == 0) trans = 1.0f;

    float w8[8];
#pragma unroll
    for (int j = 0; j < 8; ++j) {
        w8[j] = (1.0f - om8[j]) * trans;
        trans *= om8[j];
    }
    // chunk-boundary neighbors (global edges -> 0, matching the pad)
    float wprev = __shfl_up_sync(FULL, w8[7], 1);
    float wnext = __shfl_down_sync(FULL, w8[0], 1);
    if (lane == 0)  wprev = 0.0f;
    if (lane == 31) wnext = 0.0f;

    // =================================================================
    // REWEIGHT in registers (maxblur + floor; segment scale 0.5 cancels
    // bit-exactly under normalization). In-place with rolling original.
    // =================================================================
    float csum = 0.0f;
    float prevO = wprev;
#pragma unroll
    for (int j = 0; j < 8; ++j) {
        float cur = w8[j];
        float nxt = (j < 7) ? w8[j + 1] : wnext;
        float v = fmaf(0.5f, fmaxf(prevO, cur) + fmaxf(cur, nxt), FLOORW);
        w8[j] = v;
        csum += v;
        prevO = cur;
    }
    // inclusive sum scan of reweighted chunk sums; Ic kept for phase-1 search
    float Ic = csum;
#pragma unroll
    for (int off = 1; off < 32; off <<= 1) {
        float v = __shfl_up_sync(FULL, Ic, off);
        if (lane >= off) Ic += v;
    }
    float total = __shfl_sync(FULL, Ic, 31);
    float run   = __shfl_up_sync(FULL, Ic, 1);
    if (lane == 0) run = 0.0f;

    // inclusive cumsum, packed into two 128-bit shared stores
    float4 pa, pb;
    run += w8[0]; pa.x = run;  run += w8[1]; pa.y = run;
    run += w8[2]; pa.z = run;  run += w8[3]; pa.w = run;
    run += w8[4]; pb.x = run;  run += w8[5]; pb.y = run;
    run += w8[6]; pb.z = run;  run += w8[7]; pb.w = run;
    {
        float4* row = (float4*)&sCD[w][lane * 8];
        row[0] = pa; row[1] = pb;
    }
    __syncwarp();

    // =================================================================
    // IMPORTANCE SAMPLING on INCLUSIVE cumsum pi[0..255].
    // Phase 1: 5-step SHFL.IDX search over 32 chunk sums (Ic).
    // Phase 2: 3-step LDS search inside the 8-entry chunk.
    // Invariant: pi[lo-1] <= u < pi[lo]  (pi[-1] := 0).
    // =================================================================
    const float* pi = sCD[w];
    float ustep = total * (1.0f / 128.0f);
    float ubase = (float)(lane * 4) * ustep;
    float q4[4];
#pragma unroll
    for (int j = 0; j < 4; ++j) {
        float u = fmaf((float)j + 0.5f, ustep, ubase);
        int c = 0;
#pragma unroll
        for (int s = 16; s; s >>= 1) {
            float v = __shfl_sync(FULL, Ic, c + s - 1);
            if (v <= u) c += s;
        }
        int lo = c * 8;
#pragma unroll
        for (int s = 4; s; s >>= 1)
            if (pi[lo + s - 1] <= u) lo += s;
        int bl = max(lo - 1, 0);
        float c0 = pi[bl], c1 = pi[lo];
        float t = (u - c0) * rcpa(c1 - c0);
        t = (lo == 0) ? 0.0f : t;             // degenerate first bin -> q = -128
        q4[j] = (float)(bl - 128) + t;
    }

    // =================================================================
    // FINE: 4 contiguous samples per lane; deltas via regs + 1 shfl.
    // Branchless contraction: m = min(rsqrt(n2),1), f = (2-m)m, ss = n2 f^2.
    // rgb accumulated as raw wf*tanh (0.5*x+0.5 folded into epilogue).
    // =================================================================
    float qnext = __shfl_down_sync(FULL, q4[0], 1);
    float hbx = 0.05f * dx, hby = 0.05f * dy, hbz = 0.05f * dz;

    float om4[4], tr4[4], tg4[4], tb4[4], rz4[4];
#pragma unroll
    for (int j = 0; j < 4; ++j) {
        float q  = q4[j];
        float dq = (j < 3) ? (q4[j + 1] - q)
                           : ((lane == 31) ? 0.0f : (qnext - q));
        float zf  = ex2(q * CSTEP);
        rz4[j]    = rcpa(zf);
        float x   = fmaf(dx, zf, ox), y = fmaf(dy, zf, oy), zz = fmaf(dz, zf, oz);
        float n2  = fmaf(zf, zf + b, a);
        float m   = fminf(rsqa(n2), 1.0f);
        float f   = (2.0f - m) * m;           // 1 inside, (2-1/n)/n outside
        float ss  = n2 * f * f;               // n2 inside, g^2 outside
        float hf  = 0.5f * f;
        tr4[j] = tanha(fmaf(x,  hf, hbx));
        tg4[j] = tanha(fmaf(y,  hf, hby));
        tb4[j] = tanha(fmaf(zz, hf, hbz));
        float e1 = ex2(ss * SSC);
        om4[j] = ex2(e1 * (dq * EC));   // dq==0 -> om==1 (last sample)
    }
    float cp2 = (om4[0] * om4[1]) * (om4[2] * om4[3]);
    float fincl = cp2;
#pragma unroll
    for (int off = 1; off < 32; off <<= 1) {
        float v = __shfl_up_sync(FULL, fincl, off);
        if (lane >= off) fincl *= v;
    }
    float rem    = __shfl_sync(FULL, fincl, 31);   // = 1 - sum(wf) analytically
    float ftrans = __shfl_up_sync(FULL, fincl, 1);
    if (lane == 0) ftrans = 1.0f;

    const long long N3  = (long long)N * 3;
    const long long NWF = (long long)N * SFINE;
    float* __restrict__ out_img = out;
    float* __restrict__ out_wf  = out + N3;
    float* __restrict__ out_zv  = out + N3 + NWF;
    float* __restrict__ out_inv = out + N3 + 2 * NWF;

    float wf4[4], zv4[4];
    float A = 0.0f, B = 0.0f, C = 0.0f, D = 0.0f;   // str, stg, stb, invd
#pragma unroll
    for (int j = 0; j < 4; ++j) {
        float wf = (1.0f - om4[j]) * ftrans;
        ftrans *= om4[j];
        wf4[j] = wf;
        zv4[j] = fmaf(q4[j], HZSTEP, 0.5f);   // (zlf - lo)/(hi - lo)
        A = fmaf(wf, tr4[j], A);
        B = fmaf(wf, tg4[j], B);
        C = fmaf(wf, tb4[j], C);
        D = fmaf(wf, rz4[j], D);
    }
    if ((N & 3) == 0) {
        ((float4*)out_wf)[(long long)ray * 32 + lane] =
            make_float4(wf4[0], wf4[1], wf4[2], wf4[3]);
        ((float4*)out_zv)[(long long)ray * 32 + lane] =
            make_float4(zv4[0], zv4[1], zv4[2], zv4[3]);
    } else {
#pragma unroll
        for (int j = 0; j < 4; ++j) {
            out_wf[(long long)ray * SFINE + lane * 4 + j] = wf4[j];
            out_zv[(long long)ray * SFINE + lane * 4 + j] = zv4[j];
        }
    }

    // ---- routed 4-value warp reduction (6 shfl total) ----
    // step xor1: even lanes accumulate A,C; odd accumulate B,D
    float s1 = (lane & 1) ? A : B;
    float r1 = __shfl_xor_sync(FULL, s1, 1);
    if (lane & 1) B += r1; else A += r1;
    float s2 = (lane & 1) ? C : D;
    float r2 = __shfl_xor_sync(FULL, s2, 1);
    if (lane & 1) D += r2; else C += r2;
    // step xor2: lane&3==t keeps value t, gives away its other value
    bool hi = (lane & 2) != 0, odd = (lane & 1) != 0;
    float acc = hi ? (odd ? D : C) : (odd ? B : A);
    float oth = hi ? (odd ? B : A) : (odd ? D : C);
    acc += __shfl_xor_sync(FULL, oth, 2);
    // plain butterflies across 4-lane groups
    acc += __shfl_xor_sync(FULL, acc, 4);
    acc += __shfl_xor_sync(FULL, acc, 8);
    acc += __shfl_xor_sync(FULL, acc, 16);
    // lane t in {0,1,2}: image channel t; lane 3: invdepth
    if (lane < 4) {
        if (lane == 3) {
            out_inv[ray] = acc;
        } else {
            float bgc = (lane == 0) ? bgx : (lane == 1) ? bgy : bgz;
            // image_c = 0.5*sum(wf*tanh_c) + 0.5*wsum + rem*bg_c ; wsum = 1-rem
            out_img[(long long)ray * 3 + lane] =
                fmaf(rem, bgc, fmaf(0.5f, acc, 0.5f * (1.0f - rem)));
        }
    }
}

extern "C" void kernel_launch(void* const* d_in, const int* in_sizes, int n_in,
                              void* d_out, int out_size) {
    const float* rays_o = (const float*)d_in[0];
    const float* rays_d = (const float*)d_in[1];
    const float* bg     = (const float*)d_in[2];
    float* out = (float*)d_out;
    int N = in_sizes[0] / 3;

    int blocks = (N + WPB - 1) / WPB;
    nerf_kernel<<<blocks, WPB * 32>>>(rays_o, rays_d, bg, out, N);
}

// round 14
// speedup vs baseline: 1.0619x; 1.0619x over previous
#include <cuda_runtime.h>

#define SCOARSE 256
#define SFINE   128
#define WPB     8
#define ZSTEP   0.0078125f          // exact log10 step of coarse grid
#define HZSTEP  0.00390625f         // ZSTEP/2
#define FLOORW  3.90625e-7f         // 1e-4 / 256
#define CSTEP   0.025952563f        // ZSTEP * log2(10)
#define ZMUL    1.0181517217f       // 10^ZSTEP
#define SSC     (-5.7707801636f)    // -4 * log2(e)
#define EC      (-0.2817763752f)    // -25 * ZSTEP * log2(e): om-arg scale per q-unit

__device__ __forceinline__ float ex2(float x)   { float r; asm("ex2.approx.f32 %0, %1;"   : "=f"(r) : "f"(x)); return r; }
__device__ __forceinline__ float rcpa(float x)  { float r; asm("rcp.approx.f32 %0, %1;"   : "=f"(r) : "f"(x)); return r; }
__device__ __forceinline__ float rsqa(float x)  { float r; asm("rsqrt.approx.f32 %0, %1;" : "=f"(r) : "f"(x)); return r; }
__device__ __forceinline__ float tanha(float x) { float r; asm("tanh.approx.f32 %0, %1;"  : "=f"(r) : "f"(x)); return r; }

__global__ __launch_bounds__(WPB * 32)
void nerf_kernel(const float* __restrict__ rays_o,
                 const float* __restrict__ rays_d,
                 const float* __restrict__ bg_color,
                 float* __restrict__ out, int N)
{
    const unsigned FULL = 0xffffffffu;
    const int lane = threadIdx.x & 31;
    const int w    = threadIdx.x >> 5;
    const int ray  = blockIdx.x * WPB + w;
    if (ray >= N) return;

    __shared__ float sCD[WPB][SCOARSE];   // INCLUSIVE raw cumsum (16B-aligned rows)

    // ---- ray setup ----
    float ox = rays_o[ray*3+0], oy = rays_o[ray*3+1], oz = rays_o[ray*3+2];
    float dx = rays_d[ray*3+0], dy = rays_d[ray*3+1], dz = rays_d[ray*3+2];
    float bgx = bg_color[0], bgy = bg_color[1], bgz = bg_color[2];
    {
        float inv = rsqa(dx*dx + dy*dy + dz*dz);
        dx *= inv; dy *= inv; dz *= inv;
    }
    // |o + d z|^2 = a + b z + z^2  (d normalized)
    float a  = fmaf(ox, ox, fmaf(oy, oy, oz * oz));
    float od = fmaf(ox, dx, fmaf(oy, dy, oz * dz));
    float b  = od + od;

    // =================================================================
    // COARSE: 256 samples, 8 per lane. n2 via the ray quadratic only.
    // om = 1-alpha = ex2( EC * ex2(SSC*ss) ). Product-scan transmittance.
    // =================================================================
    float om8[8];
    float z = ex2((float)(lane * 8 - 128) * CSTEP);
#pragma unroll
    for (int j = 0; j < 8; ++j) {
        if (j) z *= ZMUL;
        float n2 = fmaf(z, z + b, a);
        float g  = 2.0f - rsqa(n2);
        float ss = (n2 > 1.0f) ? g * g : n2;
        float e1 = ex2(ss * SSC);
        om8[j] = ex2(e1 * EC);
    }
    if (lane == 31) om8[7] = 1.0f;            // last delta = 0 -> alpha = 0
    float cp = ((om8[0]*om8[1])*(om8[2]*om8[3]))*((om8[4]*om8[5])*(om8[6]*om8[7]));

    // inclusive product scan of chunk products -> transmittance
    float incl = cp;
#pragma unroll
    for (int off = 1; off < 32; off <<= 1) {
        float v = __shfl_up_sync(FULL, incl, off);
        if (lane >= off) incl *= v;
    }
    float trans = __shfl_up_sync(FULL, incl, 1);
    if (lane == 0) trans = 1.0f;

    float w8[8];
#pragma unroll
    for (int j = 0; j < 8; ++j) {
        w8[j] = (1.0f - om8[j]) * trans;
        trans *= om8[j];
    }
    // chunk-boundary neighbors (global edges -> 0, matching the pad)
    float wprev = __shfl_up_sync(FULL, w8[7], 1);
    float wnext = __shfl_down_sync(FULL, w8[0], 1);
    if (lane == 0)  wprev = 0.0f;
    if (lane == 31) wnext = 0.0f;

    // =================================================================
    // REWEIGHT in registers (maxblur + floor; segment scale 0.5 cancels
    // bit-exactly under normalization). In-place with rolling original.
    // =================================================================
    float csum = 0.0f;
    float prevO = wprev;
#pragma unroll
    for (int j = 0; j < 8; ++j) {
        float cur = w8[j];
        float nxt = (j < 7) ? w8[j + 1] : wnext;
        float v = fmaf(0.5f, fmaxf(prevO, cur) + fmaxf(cur, nxt), FLOORW);
        w8[j] = v;
        csum += v;
        prevO = cur;
    }
    // inclusive sum scan of reweighted chunk sums; Ic kept for phase-1 search
    float Ic = csum;
#pragma unroll
    for (int off = 1; off < 32; off <<= 1) {
        float v = __shfl_up_sync(FULL, Ic, off);
        if (lane >= off) Ic += v;
    }
    float total = __shfl_sync(FULL, Ic, 31);
    float run   = __shfl_up_sync(FULL, Ic, 1);
    if (lane == 0) run = 0.0f;

    // inclusive cumsum, packed into two 128-bit shared stores
    float4 pa, pb;
    run += w8[0]; pa.x = run;  run += w8[1]; pa.y = run;
    run += w8[2]; pa.z = run;  run += w8[3]; pa.w = run;
    run += w8[4]; pb.x = run;  run += w8[5]; pb.y = run;
    run += w8[6]; pb.z = run;  run += w8[7]; pb.w = run;
    {
        float4* row = (float4*)&sCD[w][lane * 8];
        row[0] = pa; row[1] = pb;
    }
    __syncwarp();

    // =================================================================
    // IMPORTANCE SAMPLING on INCLUSIVE cumsum pi[0..255].
    // Phase 1: 5-step SHFL.IDX search over 32 chunk sums (Ic).
    // Phase 2: 3-step LDS search inside the 8-entry chunk.
    // Invariant: pi[lo-1] <= u < pi[lo]  (pi[-1] := 0).
    // =================================================================
    const float* pi = sCD[w];
    float ustep = total * (1.0f / 128.0f);
    float ubase = (float)(lane * 4) * ustep;
    float q4[4];
#pragma unroll
    for (int j = 0; j < 4; ++j) {
        float u = fmaf((float)j + 0.5f, ustep, ubase);
        int c = 0;
#pragma unroll
        for (int s = 16; s; s >>= 1) {
            float v = __shfl_sync(FULL, Ic, c + s - 1);
            if (v <= u) c += s;
        }
        int lo = c * 8;
#pragma unroll
        for (int s = 4; s; s >>= 1)
            if (pi[lo + s - 1] <= u) lo += s;
        int bl = max(lo - 1, 0);
        float c0 = pi[bl], c1 = pi[lo];
        float t = (u - c0) * rcpa(c1 - c0);
        t = (lo == 0) ? 0.0f : t;             // degenerate first bin -> q = -128
        q4[j] = (float)(bl - 128) + t;
    }

    // =================================================================
    // FINE: 4 contiguous samples per lane; deltas via regs + 1 shfl.
    // Branchless contraction: m = min(rsqrt(n2),1), f = (2-m)m, ss = n2 f^2.
    // rgb accumulated as raw wf*tanh (0.5*x+0.5 folded into epilogue).
    // =================================================================
    float qnext = __shfl_down_sync(FULL, q4[0], 1);
    float hbx = 0.05f * dx, hby = 0.05f * dy, hbz = 0.05f * dz;

    float om4[4], tr4[4], tg4[4], tb4[4], rz4[4];
#pragma unroll
    for (int j = 0; j < 4; ++j) {
        float q  = q4[j];
        float dq = (j < 3) ? (q4[j + 1] - q)
                           : ((lane == 31) ? 0.0f : (qnext - q));
        float zf  = ex2(q * CSTEP);
        rz4[j]    = rcpa(zf);
        float x   = fmaf(dx, zf, ox), y = fmaf(dy, zf, oy), zz = fmaf(dz, zf, oz);
        float n2  = fmaf(zf, zf + b, a);
        float m   = fminf(rsqa(n2), 1.0f);
        float f   = (2.0f - m) * m;           // 1 inside, (2-1/n)/n outside
        float ss  = n2 * f * f;               // n2 inside, g^2 outside
        float hf  = 0.5f * f;
        tr4[j] = tanha(fmaf(x,  hf, hbx));
        tg4[j] = tanha(fmaf(y,  hf, hby));
        tb4[j] = tanha(fmaf(zz, hf, hbz));
        float e1 = ex2(ss * SSC);
        om4[j] = ex2(e1 * (dq * EC));   // dq==0 -> om==1 (last sample)
    }
    float cp2 = (om4[0] * om4[1]) * (om4[2] * om4[3]);
    float fincl = cp2;
#pragma unroll
    for (int off = 1; off < 32; off <<= 1) {
        float v = __shfl_up_sync(FULL, fincl, off);
        if (lane >= off) fincl *= v;
    }
    float rem    = __shfl_sync(FULL, fincl, 31);   // = 1 - sum(wf) analytically
    float ftrans = __shfl_up_sync(FULL, fincl, 1);
    if (lane == 0) ftrans = 1.0f;

    const long long N3  = (long long)N * 3;
    const long long NWF = (long long)N * SFINE;
    float* __restrict__ out_img = out;
    float* __restrict__ out_wf  = out + N3;
    float* __restrict__ out_zv  = out + N3 + NWF;
    float* __restrict__ out_inv = out + N3 + 2 * NWF;

    float wf4[4], zv4[4];
    float str = 0.0f, stg = 0.0f, stb = 0.0f, invd = 0.0f;
#pragma unroll
    for (int j = 0; j < 4; ++j) {
        float wf = (1.0f - om4[j]) * ftrans;
        ftrans *= om4[j];
        wf4[j] = wf;
        zv4[j] = fmaf(q4[j], HZSTEP, 0.5f);   // (zlf - lo)/(hi - lo)
        str  = fmaf(wf, tr4[j], str);
        stg  = fmaf(wf, tg4[j], stg);
        stb  = fmaf(wf, tb4[j], stb);
        invd = fmaf(wf, rz4[j], invd);
    }
    if ((N & 3) == 0) {
        ((float4*)out_wf)[(long long)ray * 32 + lane] =
            make_float4(wf4[0], wf4[1], wf4[2], wf4[3]);
        ((float4*)out_zv)[(long long)ray * 32 + lane] =
            make_float4(zv4[0], zv4[1], zv4[2], zv4[3]);
    } else {
#pragma unroll
        for (int j = 0; j < 4; ++j) {
            out_wf[(long long)ray * SFINE + lane * 4 + j] = wf4[j];
            out_zv[(long long)ray * SFINE + lane * 4 + j] = zv4[j];
        }
    }
    // 4-chain butterfly reduction (independent chains -> ILP 4; the routed
    // 6-shfl variant measured SLOWER in R12: serial chain + predication)
#pragma unroll
    for (int off = 16; off > 0; off >>= 1) {
        str  += __shfl_xor_sync(FULL, str,  off);
        stg  += __shfl_xor_sync(FULL, stg,  off);
        stb  += __shfl_xor_sync(FULL, stb,  off);
        invd += __shfl_xor_sync(FULL, invd, off);
    }
    if (lane == 0) {
        float hw = 0.5f * (1.0f - rem);
        // image_c = 0.5*sum(wf*tanh_c) + 0.5*wsum + rem*bg_c ; wsum = 1-rem
        out_img[(long long)ray * 3 + 0] = fmaf(rem, bgx, fmaf(0.5f, str, hw));
        out_img[(long long)ray * 3 + 1] = fmaf(rem, bgy, fmaf(0.5f, stg, hw));
        out_img[(long long)ray * 3 + 2] = fmaf(rem, bgz, fmaf(0.5f, stb, hw));
        out_inv[ray] = invd;
    }
}

extern "C" void kernel_launch(void* const* d_in, const int* in_sizes, int n_in,
                              void* d_out, int out_size) {
    const float* rays_o = (const float*)d_in[0];
    const float* rays_d = (const float*)d_in[1];
    const float* bg     = (const float*)d_in[2];
    float* out = (float*)d_out;
    int N = in_sizes[0] / 3;

    int blocks = (N + WPB - 1) / WPB;
    nerf_kernel<<<blocks, WPB * 32>>>(rays_o, rays_d, bg, out, N);
}

// round 15
// speedup vs baseline: 1.0711x; 1.0087x over previous
#include <cuda_runtime.h>

#define SCOARSE 256
#define SFINE   128
#define WPB     8
#define ZSTEP   0.0078125f          // exact log10 step of coarse grid
#define HZSTEP  0.00390625f         // ZSTEP/2
#define FLOORW  3.90625e-7f         // 1e-4 / 256
#define CSTEP   0.025952563f        // ZSTEP * log2(10)
#define ZMUL    1.0181517217f       // 10^ZSTEP
#define SSC     (-5.7707801636f)    // -4 * log2(e)
#define EC      (-0.2817763752f)    // -25 * ZSTEP * log2(e): om-arg scale per q-unit

__device__ __forceinline__ float ex2(float x)   { float r; asm("ex2.approx.f32 %0, %1;"   : "=f"(r) : "f"(x)); return r; }
__device__ __forceinline__ float rcpa(float x)  { float r; asm("rcp.approx.f32 %0, %1;"   : "=f"(r) : "f"(x)); return r; }
__device__ __forceinline__ float rsqa(float x)  { float r; asm("rsqrt.approx.f32 %0, %1;" : "=f"(r) : "f"(x)); return r; }
__device__ __forceinline__ float tanha(float x) { float r; asm("tanh.approx.f32 %0, %1;"  : "=f"(r) : "f"(x)); return r; }

__global__ __launch_bounds__(WPB * 32)
void nerf_kernel(const float* __restrict__ rays_o,
                 const float* __restrict__ rays_d,
                 const float* __restrict__ bg_color,
                 float* __restrict__ out, int N)
{
    const unsigned FULL = 0xffffffffu;
    const int lane = threadIdx.x & 31;
    const int w    = threadIdx.x >> 5;
    const int ray  = blockIdx.x * WPB + w;
    if (ray >= N) return;

    __shared__ float sCD[WPB][SCOARSE];   // INCLUSIVE raw cumsum (16B-aligned rows)

    // ---- ray setup ----
    float ox = rays_o[ray*3+0], oy = rays_o[ray*3+1], oz = rays_o[ray*3+2];
    float dx = rays_d[ray*3+0], dy = rays_d[ray*3+1], dz = rays_d[ray*3+2];
    float bgx = bg_color[0], bgy = bg_color[1], bgz = bg_color[2];
    {
        float inv = rsqa(dx*dx + dy*dy + dz*dz);
        dx *= inv; dy *= inv; dz *= inv;
    }
    // |o + d z|^2 = a + b z + z^2  (d normalized)
    float a  = fmaf(ox, ox, fmaf(oy, oy, oz * oz));
    float od = fmaf(ox, dx, fmaf(oy, dy, oz * dz));
    float b  = od + od;

    // =================================================================
    // COARSE: 256 samples, 8 per lane. n2 via the ray quadratic only.
    // om = 1-alpha = ex2( EC * ex2(SSC*ss) ). Product-scan transmittance.
    // =================================================================
    float om8[8];
    float z = ex2((float)(lane * 8 - 128) * CSTEP);
#pragma unroll
    for (int j = 0; j < 8; ++j) {
        if (j) z *= ZMUL;
        float n2 = fmaf(z, z + b, a);
        float g  = 2.0f - rsqa(n2);
        float ss = (n2 > 1.0f) ? g * g : n2;
        float e1 = ex2(ss * SSC);
        om8[j] = ex2(e1 * EC);
    }
    if (lane == 31) om8[7] = 1.0f;            // last delta = 0 -> alpha = 0
    float cp = ((om8[0]*om8[1])*(om8[2]*om8[3]))*((om8[4]*om8[5])*(om8[6]*om8[7]));

    // inclusive product scan of chunk products -> transmittance
    float incl = cp;
#pragma unroll
    for (int off = 1; off < 32; off <<= 1) {
        float v = __shfl_up_sync(FULL, incl, off);
        if (lane >= off) incl *= v;
    }
    float trans = __shfl_up_sync(FULL, incl, 1);
    if (lane == 0) trans = 1.0f;

    // weights via T-chain: w_j = T_j - T_{j+1}  (2 ops/sample)
    float w8[8];
#pragma unroll
    for (int j = 0; j < 8; ++j) {
        float Tn = trans * om8[j];
        w8[j] = trans - Tn;
        trans = Tn;
    }

    // =================================================================
    // REWEIGHT via M-sequence: M_k = max(w_k, w_{k+1}),
    // v_k = 0.5*(M_{k-1} + M_k) + floor  (exact reference maxblur).
    // Local inclusive chain S doubles as the CDF (P = S + scan prefix).
    // =================================================================
    float wnext = __shfl_down_sync(FULL, w8[0], 1);
    if (lane == 31) wnext = 0.0f;
    float M[8];
#pragma unroll
    for (int j = 0; j < 7; ++j) M[j] = fmaxf(w8[j], w8[j + 1]);
    M[7] = fmaxf(w8[7], wnext);
    float Mprev = __shfl_up_sync(FULL, M[7], 1);
    if (lane == 0) Mprev = w8[0];   // M_{-1} = max(0, w_0) = w_0

    float S8[8];
    float S = 0.0f;
#pragma unroll
    for (int j = 0; j < 8; ++j) {
        float v = fmaf(0.5f, Mprev + M[j], FLOORW);
        S += v;
        S8[j] = S;
        Mprev = M[j];
    }
    // inclusive sum scan of chunk sums; Ic reused by phase-1 search
    float Ic = S;
#pragma unroll
    for (int off = 1; off < 32; off <<= 1) {
        float v = __shfl_up_sync(FULL, Ic, off);
        if (lane >= off) Ic += v;
    }
    float total = __shfl_sync(FULL, Ic, 31);
    float E     = __shfl_up_sync(FULL, Ic, 1);
    if (lane == 0) E = 0.0f;

    // global inclusive cumsum, packed into two 128-bit shared stores
    {
        float4 pa, pb;
        pa.x = S8[0] + E; pa.y = S8[1] + E; pa.z = S8[2] + E; pa.w = S8[3] + E;
        pb.x = S8[4] + E; pb.y = S8[5] + E; pb.z = S8[6] + E; pb.w = S8[7] + E;
        float4* row = (float4*)&sCD[w][lane * 8];
        row[0] = pa; row[1] = pb;
    }
    __syncwarp();

    // =================================================================
    // IMPORTANCE SAMPLING on INCLUSIVE cumsum pi[0..255].
    // Phase 1: 5-step SHFL.IDX search over 32 chunk sums (Ic).
    // Phase 2: 3-step LDS search inside the 8-entry chunk.
    // Invariant: pi[lo-1] <= u < pi[lo]  (pi[-1] := 0).
    // =================================================================
    const float* pi = sCD[w];
    float ustep = total * (1.0f / 128.0f);
    float ubase = (float)(lane * 4) * ustep;
    float q4[4];
#pragma unroll
    for (int j = 0; j < 4; ++j) {
        float u = fmaf((float)j + 0.5f, ustep, ubase);
        int c = 0;
#pragma unroll
        for (int s = 16; s; s >>= 1) {
            float v = __shfl_sync(FULL, Ic, c + s - 1);
            if (v <= u) c += s;
        }
        int lo = c * 8;
#pragma unroll
        for (int s = 4; s; s >>= 1)
            if (pi[lo + s - 1] <= u) lo += s;
        int bl = max(lo - 1, 0);
        float c0 = pi[bl], c1 = pi[lo];
        float t = (u - c0) * rcpa(c1 - c0);
        t = (lo == 0) ? 0.0f : t;             // degenerate first bin -> q = -128
        q4[j] = (float)(bl - 128) + t;
    }

    // =================================================================
    // FINE: 4 contiguous samples per lane; deltas via regs + 1 shfl.
    // Branchless contraction: m = min(rsqrt(n2),1), f = (2-m)m, ss = n2 f^2.
    // rgb accumulated as raw wf*tanh (0.5*x+0.5 folded into epilogue).
    // =================================================================
    float qnext = __shfl_down_sync(FULL, q4[0], 1);
    float hbx = 0.05f * dx, hby = 0.05f * dy, hbz = 0.05f * dz;

    float om4[4], tr4[4], tg4[4], tb4[4], rz4[4];
#pragma unroll
    for (int j = 0; j < 4; ++j) {
        float q  = q4[j];
        float dq = (j < 3) ? (q4[j + 1] - q)
                           : ((lane == 31) ? 0.0f : (qnext - q));
        float zf  = ex2(q * CSTEP);
        rz4[j]    = rcpa(zf);
        float x   = fmaf(dx, zf, ox), y = fmaf(dy, zf, oy), zz = fmaf(dz, zf, oz);
        float n2  = fmaf(zf, zf + b, a);
        float m   = fminf(rsqa(n2), 1.0f);
        float f   = (2.0f - m) * m;           // 1 inside, (2-1/n)/n outside
        float ss  = n2 * f * f;               // n2 inside, g^2 outside
        float hf  = 0.5f * f;
        tr4[j] = tanha(fmaf(x,  hf, hbx));
        tg4[j] = tanha(fmaf(y,  hf, hby));
        tb4[j] = tanha(fmaf(zz, hf, hbz));
        float e1 = ex2(ss * SSC);
        om4[j] = ex2(e1 * (dq * EC));   // dq==0 -> om==1 (last sample)
    }
    float cp2 = (om4[0] * om4[1]) * (om4[2] * om4[3]);
    float fincl = cp2;
#pragma unroll
    for (int off = 1; off < 32; off <<= 1) {
        float v = __shfl_up_sync(FULL, fincl, off);
        if (lane >= off) fincl *= v;
    }
    float rem    = __shfl_sync(FULL, fincl, 31);   // = 1 - sum(wf) analytically
    float ftrans = __shfl_up_sync(FULL, fincl, 1);
    if (lane == 0) ftrans = 1.0f;

    const long long N3  = (long long)N * 3;
    const long long NWF = (long long)N * SFINE;
    float* __restrict__ out_img = out;
    float* __restrict__ out_wf  = out + N3;
    float* __restrict__ out_zv  = out + N3 + NWF;
    float* __restrict__ out_inv = out + N3 + 2 * NWF;

    float wf4[4], zv4[4];
    float str = 0.0f, stg = 0.0f, stb = 0.0f, invd = 0.0f;
#pragma unroll
    for (int j = 0; j < 4; ++j) {
        float Tn = ftrans * om4[j];          // T-chain: wf = T - T*om
        float wf = ftrans - Tn;
        ftrans = Tn;
        wf4[j] = wf;
        zv4[j] = fmaf(q4[j], HZSTEP, 0.5f);   // (zlf - lo)/(hi - lo)
        str  = fmaf(wf, tr4[j], str);
        stg  = fmaf(wf, tg4[j], stg);
        stb  = fmaf(wf, tb4[j], stb);
        invd = fmaf(wf, rz4[j], invd);
    }
    if ((N & 3) == 0) {
        ((float4*)out_wf)[(long long)ray * 32 + lane] =
            make_float4(wf4[0], wf4[1], wf4[2], wf4[3]);
        ((float4*)out_zv)[(long long)ray * 32 + lane] =
            make_float4(zv4[0], zv4[1], zv4[2], zv4[3]);
    } else {
#pragma unroll
        for (int j = 0; j < 4; ++j) {
            out_wf[(long long)ray * SFINE + lane * 4 + j] = wf4[j];
            out_zv[(long long)ray * SFINE + lane * 4 + j] = zv4[j];
        }
    }
    // 4-chain butterfly reduction (independent chains -> ILP 4; routed
    // variant measured SLOWER in R12: serial chain + predication)
#pragma unroll
    for (int off = 16; off > 0; off >>= 1) {
        str  += __shfl_xor_sync(FULL, str,  off);
        stg  += __shfl_xor_sync(FULL, stg,  off);
        stb  += __shfl_xor_sync(FULL, stb,  off);
        invd += __shfl_xor_sync(FULL, invd, off);
    }
    if (lane == 0) {
        float hw = 0.5f * (1.0f - rem);
        // image_c = 0.5*sum(wf*tanh_c) + 0.5*wsum + rem*bg_c ; wsum = 1-rem
        out_img[(long long)ray * 3 + 0] = fmaf(rem, bgx, fmaf(0.5f, str, hw));
        out_img[(long long)ray * 3 + 1] = fmaf(rem, bgy, fmaf(0.5f, stg, hw));
        out_img[(long long)ray * 3 + 2] = fmaf(rem, bgz, fmaf(0.5f, stb, hw));
        out_inv[ray] = invd;
    }
}

extern "C" void kernel_launch(void* const* d_in, const int* in_sizes, int n_in,
                              void* d_out, int out_size) {
    const float* rays_o = (const float*)d_in[0];
    const float* rays_d = (const float*)d_in[1];
    const float* bg     = (const float*)d_in[2];
    float* out = (float*)d_out;
    int N = in_sizes[0] / 3;

    int blocks = (N + WPB - 1) / WPB;
    nerf_kernel<<<blocks, WPB * 32>>>(rays_o, rays_d, bg, out, N);
}

// round 16
// speedup vs baseline: 1.0918x; 1.0194x over previous
#include <cuda_runtime.h>

#define SCOARSE 256
#define SFINE   128
#define WPB     8
#define ZSTEP   0.0078125f          // exact log10 step of coarse grid
#define HZSTEP  0.00390625f         // ZSTEP/2
#define FLOORW  3.90625e-7f         // 1e-4 / 256
#define CSTEP   0.025952563f        // ZSTEP * log2(10)
#define NCSTEP  (-0.025952563f)     // -CSTEP
#define ZMUL    1.0181517217f       // 10^ZSTEP
#define SSC     (-5.7707801636f)    // -4 * log2(e)
#define EC      (-0.2817763752f)    // -25 * ZSTEP * log2(e): om-arg scale per q-unit

__device__ __forceinline__ float ex2(float x)   { float r; asm("ex2.approx.f32 %0, %1;"   : "=f"(r) : "f"(x)); return r; }
__device__ __forceinline__ float rcpa(float x)  { float r; asm("rcp.approx.f32 %0, %1;"   : "=f"(r) : "f"(x)); return r; }
__device__ __forceinline__ float rsqa(float x)  { float r; asm("rsqrt.approx.f32 %0, %1;" : "=f"(r) : "f"(x)); return r; }
__device__ __forceinline__ float tanha(float x) { float r; asm("tanh.approx.f32 %0, %1;"  : "=f"(r) : "f"(x)); return r; }

__global__ __launch_bounds__(WPB * 32, 7)   // cap regs at 36 -> 7 CTAs/SM
void nerf_kernel(const float* __restrict__ rays_o,
                 const float* __restrict__ rays_d,
                 const float* __restrict__ bg_color,
                 float* __restrict__ out, int N)
{
    const unsigned FULL = 0xffffffffu;
    const int lane = threadIdx.x & 31;
    const int w    = threadIdx.x >> 5;
    const int ray  = blockIdx.x * WPB + w;
    if (ray >= N) return;

    __shared__ float sCD[WPB][SCOARSE];   // INCLUSIVE raw cumsum (16B-aligned rows)

    // ---- ray setup (bg deferred to epilogue to shorten live ranges) ----
    float ox = rays_o[ray*3+0], oy = rays_o[ray*3+1], oz = rays_o[ray*3+2];
    float dx = rays_d[ray*3+0], dy = rays_d[ray*3+1], dz = rays_d[ray*3+2];
    {
        float inv = rsqa(dx*dx + dy*dy + dz*dz);
        dx *= inv; dy *= inv; dz *= inv;
    }
    // |o + d z|^2 = a + b z + z^2  (d normalized)
    float a  = fmaf(ox, ox, fmaf(oy, oy, oz * oz));
    float od = fmaf(ox, dx, fmaf(oy, dy, oz * dz));
    float b  = od + od;

    // =================================================================
    // COARSE: 256 samples, 8 per lane. n2 via the ray quadratic only.
    // om = 1-alpha = ex2( EC * ex2(SSC*ss) ). Product-scan transmittance.
    // =================================================================
    float om8[8];
    float z = ex2((float)(lane * 8 - 128) * CSTEP);
#pragma unroll
    for (int j = 0; j < 8; ++j) {
        if (j) z *= ZMUL;
        float n2 = fmaf(z, z + b, a);
        float g  = 2.0f - rsqa(n2);
        float ss = (n2 > 1.0f) ? g * g : n2;
        float e1 = ex2(ss * SSC);
        om8[j] = ex2(e1 * EC);
    }
    if (lane == 31) om8[7] = 1.0f;            // last delta = 0 -> alpha = 0
    float cp = ((om8[0]*om8[1])*(om8[2]*om8[3]))*((om8[4]*om8[5])*(om8[6]*om8[7]));

    // inclusive product scan of chunk products -> transmittance
    float incl = cp;
#pragma unroll
    for (int off = 1; off < 32; off <<= 1) {
        float v = __shfl_up_sync(FULL, incl, off);
        if (lane >= off) incl *= v;
    }
    float trans = __shfl_up_sync(FULL, incl, 1);
    if (lane == 0) trans = 1.0f;

    // weights via T-chain: w_j = T_j - T_{j+1}  (2 ops/sample)
    float w8[8];
#pragma unroll
    for (int j = 0; j < 8; ++j) {
        float Tn = trans * om8[j];
        w8[j] = trans - Tn;
        trans = Tn;
    }

    // =================================================================
    // REWEIGHT via M-sequence: M_k = max(w_k, w_{k+1}),
    // v_k = 0.5*(M_{k-1} + M_k) + floor  (exact reference maxblur).
    // Local inclusive chain S doubles as the CDF (P = S + scan prefix).
    // =================================================================
    float wnext = __shfl_down_sync(FULL, w8[0], 1);
    if (lane == 31) wnext = 0.0f;
    float M[8];
#pragma unroll
    for (int j = 0; j < 7; ++j) M[j] = fmaxf(w8[j], w8[j + 1]);
    M[7] = fmaxf(w8[7], wnext);
    float Mprev = __shfl_up_sync(FULL, M[7], 1);
    if (lane == 0) Mprev = w8[0];   // M_{-1} = max(0, w_0) = w_0

    float S8[8];
    float S = 0.0f;
#pragma unroll
    for (int j = 0; j < 8; ++j) {
        float v = fmaf(0.5f, Mprev + M[j], FLOORW);
        S += v;
        S8[j] = S;
        Mprev = M[j];
    }
    // inclusive sum scan of chunk sums; Ic reused by phase-1 search
    float Ic = S;
#pragma unroll
    for (int off = 1; off < 32; off <<= 1) {
        float v = __shfl_up_sync(FULL, Ic, off);
        if (lane >= off) Ic += v;
    }
    float total = __shfl_sync(FULL, Ic, 31);
    float E     = __shfl_up_sync(FULL, Ic, 1);
    if (lane == 0) E = 0.0f;

    // global inclusive cumsum, packed into two 128-bit shared stores
    {
        float4 pa, pb;
        pa.x = S8[0] + E; pa.y = S8[1] + E; pa.z = S8[2] + E; pa.w = S8[3] + E;
        pb.x = S8[4] + E; pb.y = S8[5] + E; pb.z = S8[6] + E; pb.w = S8[7] + E;
        float4* row = (float4*)&sCD[w][lane * 8];
        row[0] = pa; row[1] = pb;
    }
    __syncwarp();

    // =================================================================
    // IMPORTANCE SAMPLING on INCLUSIVE cumsum pi[0..255].
    // Phase 1: 5-step SHFL.IDX search over 32 chunk sums (Ic).
    // Phase 2: 3-step LDS search inside the 8-entry chunk.
    // Invariant: pi[lo-1] <= u < pi[lo]  (pi[-1] := 0).
    // =================================================================
    const float* pi = sCD[w];
    float ustep = total * (1.0f / 128.0f);
    float ubase = (float)(lane * 4) * ustep;
    float q4[4];
#pragma unroll
    for (int j = 0; j < 4; ++j) {
        float u = fmaf((float)j + 0.5f, ustep, ubase);
        int c = 0;
#pragma unroll
        for (int s = 16; s; s >>= 1) {
            float v = __shfl_sync(FULL, Ic, c + s - 1);
            if (v <= u) c += s;
        }
        int lo = c * 8;
#pragma unroll
        for (int s = 4; s; s >>= 1)
            if (pi[lo + s - 1] <= u) lo += s;
        int bl = max(lo - 1, 0);
        float c0 = pi[bl], c1 = pi[lo];
        float t = (u - c0) * rcpa(c1 - c0);
        t = (lo == 0) ? 0.0f : t;             // degenerate first bin -> q = -128
        q4[j] = (float)(bl - 128) + t;
    }

    // =================================================================
    // FINE: 4 contiguous samples per lane; deltas via regs + 1 shfl.
    // Branchless contraction: m = min(rsqrt(n2),1), f = (2-m)m, ss = n2 f^2.
    // rgb accumulated as raw wf*tanh (0.5*x+0.5 folded into epilogue).
    // 1/zf NOT kept in regs; recomputed in epilogue (reg pressure).
    // =================================================================
    float qnext = __shfl_down_sync(FULL, q4[0], 1);
    float hbx = 0.05f * dx, hby = 0.05f * dy, hbz = 0.05f * dz;

    float om4[4], tr4[4], tg4[4], tb4[4];
#pragma unroll
    for (int j = 0; j < 4; ++j) {
        float q  = q4[j];
        float dq = (j < 3) ? (q4[j + 1] - q)
                           : ((lane == 31) ? 0.0f : (qnext - q));
        float zf  = ex2(q * CSTEP);
        float x   = fmaf(dx, zf, ox), y = fmaf(dy, zf, oy), zz = fmaf(dz, zf, oz);
        float n2  = fmaf(zf, zf + b, a);
        float m   = fminf(rsqa(n2), 1.0f);
        float f   = (2.0f - m) * m;           // 1 inside, (2-1/n)/n outside
        float ss  = n2 * f * f;               // n2 inside, g^2 outside
        float hf  = 0.5f * f;
        tr4[j] = tanha(fmaf(x,  hf, hbx));
        tg4[j] = tanha(fmaf(y,  hf, hby));
        tb4[j] = tanha(fmaf(zz, hf, hbz));
        float e1 = ex2(ss * SSC);
        om4[j] = ex2(e1 * (dq * EC));   // dq==0 -> om==1 (last sample)
    }
    float cp2 = (om4[0] * om4[1]) * (om4[2] * om4[3]);
    float fincl = cp2;
#pragma unroll
    for (int off = 1; off < 32; off <<= 1) {
        float v = __shfl_up_sync(FULL, fincl, off);
        if (lane >= off) fincl *= v;
    }
    float rem    = __shfl_sync(FULL, fincl, 31);   // = 1 - sum(wf) analytically
    float ftrans = __shfl_up_sync(FULL, fincl, 1);
    if (lane == 0) ftrans = 1.0f;

    const long long N3  = (long long)N * 3;
    const long long NWF = (long long)N * SFINE;
    float* __restrict__ out_img = out;
    float* __restrict__ out_wf  = out + N3;
    float* __restrict__ out_zv  = out + N3 + NWF;
    float* __restrict__ out_inv = out + N3 + 2 * NWF;

    float wf4[4], zv4[4];
    float str = 0.0f, stg = 0.0f, stb = 0.0f, invd = 0.0f;
#pragma unroll
    for (int j = 0; j < 4; ++j) {
        float Tn = ftrans * om4[j];          // T-chain: wf = T - T*om
        float wf = ftrans - Tn;
        ftrans = Tn;
        wf4[j] = wf;
        zv4[j] = fmaf(q4[j], HZSTEP, 0.5f);   // (zlf - lo)/(hi - lo)
        str  = fmaf(wf, tr4[j], str);
        stg  = fmaf(wf, tg4[j], stg);
        stb  = fmaf(wf, tb4[j], stb);
        invd = fmaf(wf, ex2(q4[j] * NCSTEP), invd);   // 1/zf = 2^(-q*CSTEP)
    }
    if ((N & 3) == 0) {
        ((float4*)out_wf)[(long long)ray * 32 + lane] =
            make_float4(wf4[0], wf4[1], wf4[2], wf4[3]);
        ((float4*)out_zv)[(long long)ray * 32 + lane] =
            make_float4(zv4[0], zv4[1], zv4[2], zv4[3]);
    } else {
#pragma unroll
        for (int j = 0; j < 4; ++j) {
            out_wf[(long long)ray * SFINE + lane * 4 + j] = wf4[j];
            out_zv[(long long)ray * SFINE + lane * 4 + j] = zv4[j];
        }
    }

    // packed f32x2 butterfly: 2 independent 64-bit chains (ILP kept),
    // halves the add count of the 4-chain scalar version.
    unsigned long long P1, P2;
    asm("mov.b64 %0, {%1, %2};" : "=l"(P1) : "f"(str), "f"(stg));
    asm("mov.b64 %0, {%1, %2};" : "=l"(P2) : "f"(stb), "f"(invd));
#pragma unroll
    for (int off = 16; off > 0; off >>= 1) {
        unsigned long long q1 = __shfl_xor_sync(FULL, P1, off);
        unsigned long long q2 = __shfl_xor_sync(FULL, P2, off);
        asm("add.rn.f32x2 %0, %1, %2;" : "=l"(P1) : "l"(P1), "l"(q1));
        asm("add.rn.f32x2 %0, %1, %2;" : "=l"(P2) : "l"(P2), "l"(q2));
    }
    if (lane == 0) {
        asm("mov.b64 {%0, %1}, %2;" : "=f"(str), "=f"(stg) : "l"(P1));
        asm("mov.b64 {%0, %1}, %2;" : "=f"(stb), "=f"(invd) : "l"(P2));
        float hw = 0.5f * (1.0f - rem);
        // image_c = 0.5*sum(wf*tanh_c) + 0.5*wsum + rem*bg_c ; wsum = 1-rem
        out_img[(long long)ray * 3 + 0] = fmaf(rem, bg_color[0], fmaf(0.5f, str, hw));
        out_img[(long long)ray * 3 + 1] = fmaf(rem, bg_color[1], fmaf(0.5f, stg, hw));
        out_img[(long long)ray * 3 + 2] = fmaf(rem, bg_color[2], fmaf(0.5f, stb, hw));
        out_inv[ray] = invd;
    }
}

extern "C" void kernel_launch(void* const* d_in, const int* in_sizes, int n_in,
                              void* d_out, int out_size) {
    const float* rays_o = (const float*)d_in[0];
    const float* rays_d = (const float*)d_in[1];
    const float* bg     = (const float*)d_in[2];
    float* out = (float*)d_out;
    int N = in_sizes[0] / 3;

    int blocks = (N + WPB - 1) / WPB;
    nerf_kernel<<<blocks, WPB * 32>>>(rays_o, rays_d, bg, out, N);
}